// round 6
// baseline (speedup 1.0000x reference)
#include <cuda_runtime.h>
#include <math.h>
#include <float.h>
#include <stdint.h>

#define BB 16
#define DD 512
#define TT 2048
#define NQ 9
#define CS 1024
#define CD 8
#define TTILE 32
#define NTHREADS 256

// ---------------- precomputed (normalized) parameter scratch ----------------
__device__ float g_win[NQ * CD * DD];   // weight-normed in_proj  (q, c, d)
__device__ float g_wout[NQ * DD * CD];  // weight-normed out_proj (q, d, c)
__device__ float g_cbn[NQ * CS * CD];   // l2-normalized codebook
__device__ float g_csq[NQ * CS];        // sum(c_norm^2) per code

__global__ void rvq_precompute(const float* __restrict__ iv, const float* __restrict__ ig,
                               const float* __restrict__ ov, const float* __restrict__ og,
                               const float* __restrict__ cb) {
    int q = blockIdx.x;
    int tid = threadIdx.x;           // 256 threads
    int wid = tid >> 5, lane = tid & 31;

    // in_proj: 8 rows of 512, one warp per row
    if (wid < CD) {
        int c = wid;
        const float* v = iv + ((size_t)q * CD + c) * DD;
        float ss = 0.f;
        for (int d = lane; d < DD; d += 32) { float x = v[d]; ss = fmaf(x, x, ss); }
        #pragma unroll
        for (int o = 16; o > 0; o >>= 1) ss += __shfl_xor_sync(0xffffffffu, ss, o);
        float nrm = __fsqrt_rn(ss);
        float g = ig[q * CD + c];
        for (int d = lane; d < DD; d += 32)
            g_win[((size_t)q * CD + c) * DD + d] = __fdiv_rn(g * v[d], nrm);
    }
    // out_proj: 512 rows of 8
    for (int r = tid; r < DD; r += 256) {
        const float* v = ov + ((size_t)q * DD + r) * CD;
        float ss = 0.f;
        #pragma unroll
        for (int c = 0; c < CD; c++) { float x = v[c]; ss = fmaf(x, x, ss); }
        float nrm = __fsqrt_rn(ss);
        float g = og[q * DD + r];
        #pragma unroll
        for (int c = 0; c < CD; c++)
            g_wout[((size_t)q * DD + r) * CD + c] = __fdiv_rn(g * v[c], nrm);
    }
    // codebook: 1024 rows of 8, l2norm with eps, plus csq
    for (int s = tid; s < CS; s += 256) {
        const float* v = cb + ((size_t)q * CS + s) * CD;
        float ss = 0.f;
        #pragma unroll
        for (int c = 0; c < CD; c++) { float x = v[c]; ss = fmaf(x, x, ss); }
        float den = fmaxf(__fsqrt_rn(ss), 1e-12f);
        float cs2 = 0.f;
        #pragma unroll
        for (int c = 0; c < CD; c++) {
            float cn = __fdiv_rn(v[c], den);
            g_cbn[((size_t)q * CS + s) * CD + c] = cn;
            cs2 = fmaf(cn, cn, cs2);
        }
        g_csq[q * CS + s] = cs2;
    }
}

// ---------------- main fused RVQ kernel (3 CTAs/SM, tables from L2) ----------------
struct SMem {
    float res[DD][TTILE];      // 64 KB residual tile
    float zi[CD][TTILE];       // 1 KB
    float zqs[CD][TTILE];      // 1 KB
    float redb[8][TTILE];      // 1 KB
    int   redi[8][TTILE];      // 1 KB
};  // ~68 KB -> 3 CTAs/SM

__device__ __forceinline__ float dist8(float4 ca, float4 cb2,
                                       float e0, float e1, float e2, float e3,
                                       float e4, float e5, float e6, float e7,
                                       float eq, float cs) {
    float dot = e0 * ca.x;
    dot = fmaf(e1, ca.y, dot); dot = fmaf(e2, ca.z, dot); dot = fmaf(e3, ca.w, dot);
    dot = fmaf(e4, cb2.x, dot); dot = fmaf(e5, cb2.y, dot);
    dot = fmaf(e6, cb2.z, dot); dot = fmaf(e7, cb2.w, dot);
    // matches reference ((enc_sq - 2*dot) + csq)
    return fmaf(-2.0f, dot, eq) + cs;
}

__global__ void __launch_bounds__(NTHREADS, 3)
rvq_kernel(const float* __restrict__ z,
           const float* __restrict__ ib_g,
           const float* __restrict__ ob_g,
           const float* __restrict__ cbraw,
           float* __restrict__ out) {
    extern __shared__ unsigned char smraw[];
    SMem& sm = *reinterpret_cast<SMem*>(smraw);

    const int tid = threadIdx.x;
    const int b = blockIdx.y;
    const int t0 = blockIdx.x * TTILE;

    float* out_codes = out;
    float* out_zO  = out + (size_t)BB * NQ * TT;
    float* out_zis = out_zO + (size_t)BB * DD * TT;
    float* out_zqs = out_zis + (size_t)BB * NQ * CD * TT;
    float* out_zos = out_zqs + (size_t)BB * NQ * CD * TT;

    // ---- load residual tile (vectorized): 512 x 32 ----
    const float* zb = z + (size_t)b * DD * TT + t0;
    {
        float4* res4 = reinterpret_cast<float4*>(&sm.res[0][0]);
        for (int f = tid; f < DD * (TTILE / 4); f += NTHREADS) {
            int d = f >> 3, j = f & 7;
            res4[f] = reinterpret_cast<const float4*>(zb + (size_t)d * TT)[j];
        }
    }

    const int t  = tid & (TTILE - 1);   // 0..31 (= lane)
    const int hi = tid >> 5;            // 0..7  (c / chunk / d-group; = warp id)

    for (int q = 0; q < NQ; q++) {
        __syncthreads();   // res settled

        // ---- z_i = w_in @ residual + ib  (warp hi = channel, lane = t) ----
        float ziv;
        {
            const float4* win4 = reinterpret_cast<const float4*>(
                g_win + ((size_t)q * CD + hi) * DD);
            float a0 = 0.f, a1 = 0.f, a2 = 0.f, a3 = 0.f;
            #pragma unroll 8
            for (int i = 0; i < DD / 4; i++) {
                float4 w = __ldg(&win4[i]);          // uniform LDG (1 req/warp, L2-hot)
                int d = 4 * i;
                a0 = fmaf(w.x, sm.res[d + 0][t], a0);
                a1 = fmaf(w.y, sm.res[d + 1][t], a1);
                a2 = fmaf(w.z, sm.res[d + 2][t], a2);
                a3 = fmaf(w.w, sm.res[d + 3][t], a3);
            }
            ziv = ((a0 + a1) + (a2 + a3)) + __ldg(&ib_g[q * CD + hi]);
            sm.zi[hi][t] = ziv;
            out_zis[(((size_t)b * NQ + q) * CD + hi) * TT + t0 + t] = ziv;
        }
        __syncthreads();

        // ---- NN search: redundant per-thread norm, then 128 codes (chunk=hi) ----
        {
            float z0 = sm.zi[0][t], z1 = sm.zi[1][t], z2 = sm.zi[2][t], z3 = sm.zi[3][t];
            float z4 = sm.zi[4][t], z5 = sm.zi[5][t], z6 = sm.zi[6][t], z7 = sm.zi[7][t];
            float ss = z0 * z0;
            ss = fmaf(z1, z1, ss); ss = fmaf(z2, z2, ss); ss = fmaf(z3, z3, ss);
            ss = fmaf(z4, z4, ss); ss = fmaf(z5, z5, ss); ss = fmaf(z6, z6, ss);
            ss = fmaf(z7, z7, ss);
            float den = fmaxf(__fsqrt_rn(ss), 1e-12f);
            float e0 = __fdiv_rn(z0, den), e1 = __fdiv_rn(z1, den);
            float e2 = __fdiv_rn(z2, den), e3 = __fdiv_rn(z3, den);
            float e4 = __fdiv_rn(z4, den), e5 = __fdiv_rn(z5, den);
            float e6 = __fdiv_rn(z6, den), e7 = __fdiv_rn(z7, den);
            float eq = e0 * e0;
            eq = fmaf(e1, e1, eq); eq = fmaf(e2, e2, eq); eq = fmaf(e3, e3, eq);
            eq = fmaf(e4, e4, eq); eq = fmaf(e5, e5, eq); eq = fmaf(e6, e6, eq);
            eq = fmaf(e7, e7, eq);

            const float4* cb4 = reinterpret_cast<const float4*>(g_cbn + (size_t)q * CS * CD);
            const float4* cq4 = reinterpret_cast<const float4*>(g_csq + (size_t)q * CS);
            const int s0 = hi * (CS / 8);
            float b0 = FLT_MAX, b1 = FLT_MAX, b2 = FLT_MAX, b3 = FLT_MAX;
            int   i0 = 0, i1 = 0, i2 = 0, i3 = 0;
            #pragma unroll 2
            for (int s = s0; s < s0 + CS / 8; s += 4) {
                float4 cs4 = __ldg(&cq4[s >> 2]);     // uniform LDG, 4 codes
                float4 cA0 = __ldg(&cb4[2 * s + 0]), cA1 = __ldg(&cb4[2 * s + 1]);
                float4 cB0 = __ldg(&cb4[2 * s + 2]), cB1 = __ldg(&cb4[2 * s + 3]);
                float4 cC0 = __ldg(&cb4[2 * s + 4]), cC1 = __ldg(&cb4[2 * s + 5]);
                float4 cD0 = __ldg(&cb4[2 * s + 6]), cD1 = __ldg(&cb4[2 * s + 7]);
                float dA = dist8(cA0, cA1, e0,e1,e2,e3,e4,e5,e6,e7, eq, cs4.x);
                float dB = dist8(cB0, cB1, e0,e1,e2,e3,e4,e5,e6,e7, eq, cs4.y);
                float dC = dist8(cC0, cC1, e0,e1,e2,e3,e4,e5,e6,e7, eq, cs4.z);
                float dDv= dist8(cD0, cD1, e0,e1,e2,e3,e4,e5,e6,e7, eq, cs4.w);
                if (dA < b0) { b0 = dA; i0 = s; }
                if (dB < b1) { b1 = dB; i1 = s + 1; }
                if (dC < b2) { b2 = dC; i2 = s + 2; }
                if (dDv< b3) { b3 = dDv; i3 = s + 3; }
            }
            // merge 4 strided chains, exact first-index tie-break
            if (b1 < b0 || (b1 == b0 && i1 < i0)) { b0 = b1; i0 = i1; }
            if (b2 < b0 || (b2 == b0 && i2 < i0)) { b0 = b2; i0 = i2; }
            if (b3 < b0 || (b3 == b0 && i3 < i0)) { b0 = b3; i0 = i3; }
            sm.redb[hi][t] = b0;
            sm.redi[hi][t] = i0;
        }
        __syncthreads();

        // ---- z_q: redundant argmin merge + straight-through  (c = hi, lane = t) ----
        {
            float bb = sm.redb[0][t]; int bi = sm.redi[0][t];
            #pragma unroll
            for (int g = 1; g < 8; g++) {
                float v = sm.redb[g][t];
                if (v < bb) { bb = v; bi = sm.redi[g][t]; }   // chunks ascending
            }
            if (hi == 0)
                out_codes[((size_t)b * NQ + q) * TT + t0 + t] = (float)bi;
            float raw = __ldg(&cbraw[((size_t)q * CS + bi) * CD + hi]);
            float zqv = ziv + (raw - ziv);
            sm.zqs[hi][t] = zqv;
            out_zqs[(((size_t)b * NQ + q) * CD + hi) * TT + t0 + t] = zqv;
        }
        __syncthreads();

        // ---- z_o = w_out @ z_q + ob ; residual -= z_o  (dgroup = hi, lane = t) ----
        {
            const float q0 = sm.zqs[0][t], q1 = sm.zqs[1][t], q2 = sm.zqs[2][t], q3 = sm.zqs[3][t];
            const float q4 = sm.zqs[4][t], q5 = sm.zqs[5][t], q6 = sm.zqs[6][t], q7 = sm.zqs[7][t];
            const float4* wo4 = reinterpret_cast<const float4*>(g_wout + (size_t)q * DD * CD);
            const float* obp = ob_g + (size_t)q * DD;
            float* zosb = out_zos + (((size_t)b * NQ + q) * DD) * TT + t0 + t;
            const int dbase = hi * 64;
            #pragma unroll 4
            for (int i = 0; i < 64; i++) {
                int d = dbase + i;
                float4 wa = __ldg(&wo4[2 * d]), wb = __ldg(&wo4[2 * d + 1]);  // uniform LDG
                float dot = q0 * wa.x;
                dot = fmaf(q1, wa.y, dot); dot = fmaf(q2, wa.z, dot); dot = fmaf(q3, wa.w, dot);
                dot = fmaf(q4, wb.x, dot); dot = fmaf(q5, wb.y, dot);
                dot = fmaf(q6, wb.z, dot); dot = fmaf(q7, wb.w, dot);
                float zo = dot + __ldg(&obp[d]);
                zosb[(size_t)d * TT] = zo;
                sm.res[d][t] = sm.res[d][t] - zo;
            }
        }
    }

    __syncthreads();
    // ---- z_O = z - residual_final ----
    {
        const float* zsrc = zb + t;
        float* zOb = out_zO + (size_t)b * DD * TT + t0 + t;
        const int dbase = hi * 64;
        #pragma unroll 4
        for (int i = 0; i < 64; i++) {
            int d = dbase + i;
            zOb[(size_t)d * TT] = zsrc[(size_t)d * TT] - sm.res[d][t];
        }
    }
}

extern "C" void kernel_launch(void* const* d_in, const int* in_sizes, int n_in,
                              void* d_out, int out_size) {
    const float* z    = (const float*)d_in[0];
    const float* in_v = (const float*)d_in[1];
    const float* in_g = (const float*)d_in[2];
    const float* in_b = (const float*)d_in[3];
    const float* out_v= (const float*)d_in[4];
    const float* out_g= (const float*)d_in[5];
    const float* out_b= (const float*)d_in[6];
    const float* cb   = (const float*)d_in[7];
    float* out = (float*)d_out;

    rvq_precompute<<<NQ, 256>>>(in_v, in_g, out_v, out_g, cb);

    cudaFuncSetAttribute(rvq_kernel, cudaFuncAttributeMaxDynamicSharedMemorySize,
                         (int)sizeof(SMem));
    dim3 grid(TT / TTILE, BB);
    rvq_kernel<<<grid, NTHREADS, sizeof(SMem)>>>(z, in_b, out_b, cb, out);
}

// round 7
// speedup vs baseline: 1.0689x; 1.0689x over previous
#include <cuda_runtime.h>
#include <math.h>
#include <float.h>
#include <stdint.h>

#define BB 16
#define DD 512
#define TT 2048
#define NQ 9
#define CS 1024
#define CD 8
#define TTILE 64
#define HTILE 32
#define NTHREADS 512

// ---------------- precomputed (normalized) parameter scratch ----------------
__device__ float g_win[NQ * CD * DD];   // weight-normed in_proj  (q, c, d)
__device__ float g_wout[NQ * DD * CD];  // weight-normed out_proj (q, d, c)
__device__ float g_cbn[NQ * CS * CD];   // l2-normalized codebook
__device__ float g_csq[NQ * CS];        // sum(c_norm^2) per code

__global__ void rvq_precompute(const float* __restrict__ iv, const float* __restrict__ ig,
                               const float* __restrict__ ov, const float* __restrict__ og,
                               const float* __restrict__ cb) {
    int q = blockIdx.x;
    int tid = threadIdx.x;           // 256 threads
    int wid = tid >> 5, lane = tid & 31;

    // in_proj: 8 rows of 512, one warp per row
    if (wid < CD) {
        int c = wid;
        const float* v = iv + ((size_t)q * CD + c) * DD;
        float ss = 0.f;
        for (int d = lane; d < DD; d += 32) { float x = v[d]; ss = fmaf(x, x, ss); }
        #pragma unroll
        for (int o = 16; o > 0; o >>= 1) ss += __shfl_xor_sync(0xffffffffu, ss, o);
        float nrm = __fsqrt_rn(ss);
        float g = ig[q * CD + c];
        for (int d = lane; d < DD; d += 32)
            g_win[((size_t)q * CD + c) * DD + d] = __fdiv_rn(g * v[d], nrm);
    }
    // out_proj: 512 rows of 8
    for (int r = tid; r < DD; r += 256) {
        const float* v = ov + ((size_t)q * DD + r) * CD;
        float ss = 0.f;
        #pragma unroll
        for (int c = 0; c < CD; c++) { float x = v[c]; ss = fmaf(x, x, ss); }
        float nrm = __fsqrt_rn(ss);
        float g = og[q * DD + r];
        #pragma unroll
        for (int c = 0; c < CD; c++)
            g_wout[((size_t)q * DD + r) * CD + c] = __fdiv_rn(g * v[c], nrm);
    }
    // codebook: 1024 rows of 8, l2norm with eps, plus csq
    for (int s = tid; s < CS; s += 256) {
        const float* v = cb + ((size_t)q * CS + s) * CD;
        float ss = 0.f;
        #pragma unroll
        for (int c = 0; c < CD; c++) { float x = v[c]; ss = fmaf(x, x, ss); }
        float den = fmaxf(__fsqrt_rn(ss), 1e-12f);
        float cs2 = 0.f;
        #pragma unroll
        for (int c = 0; c < CD; c++) {
            float cn = __fdiv_rn(v[c], den);
            g_cbn[((size_t)q * CS + s) * CD + c] = cn;
            cs2 = fmaf(cn, cn, cs2);
        }
        g_csq[q * CS + s] = cs2;
    }
}

// ---------------- main fused RVQ kernel (split-CTA: two drifting 256-thread halves) ----------------
struct SMem {
    float4 cbn4[CS * 2];          // 32 KB  normalized codebook (shared read-only)
    float  res[DD][TTILE];        // 128 KB residual tile (halves touch disjoint t columns)
    float  win[CD][DD];           // 16 KB
    float  wout[DD][CD];          // 16 KB
    float4 csq4[CS / 4];          // 4 KB
    float  ob[DD];                // 2 KB
    float  zi[2][CD][HTILE];      // 2 KB  per-half scratch
    float  zqs[2][CD][HTILE];     // 2 KB
    float  redb[2][8][HTILE];     // 2 KB
    int    redi[2][8][HTILE];     // 2 KB
    float  ib[CD];
};  // ~206 KB

__device__ __forceinline__ void bar_half(int H) {
    asm volatile("bar.sync %0, 256;" :: "r"(1 + H) : "memory");
}

__device__ __forceinline__ float dist8(float4 ca, float4 cb2,
                                       float e0, float e1, float e2, float e3,
                                       float e4, float e5, float e6, float e7,
                                       float eq, float cs) {
    float dot = e0 * ca.x;
    dot = fmaf(e1, ca.y, dot); dot = fmaf(e2, ca.z, dot); dot = fmaf(e3, ca.w, dot);
    dot = fmaf(e4, cb2.x, dot); dot = fmaf(e5, cb2.y, dot);
    dot = fmaf(e6, cb2.z, dot); dot = fmaf(e7, cb2.w, dot);
    // matches reference ((enc_sq - 2*dot) + csq)
    return fmaf(-2.0f, dot, eq) + cs;
}

__global__ void __launch_bounds__(NTHREADS, 1)
rvq_kernel(const float* __restrict__ z,
           const float* __restrict__ ib_g,
           const float* __restrict__ ob_g,
           const float* __restrict__ cbraw,
           float* __restrict__ out) {
    extern __shared__ unsigned char smraw[];
    SMem& sm = *reinterpret_cast<SMem*>(smraw);

    const int tid = threadIdx.x;
    const int b = blockIdx.y;
    const int t0 = blockIdx.x * TTILE;

    float* out_codes = out;
    float* out_zO  = out + (size_t)BB * NQ * TT;
    float* out_zis = out_zO + (size_t)BB * DD * TT;
    float* out_zqs = out_zis + (size_t)BB * NQ * CD * TT;
    float* out_zos = out_zqs + (size_t)BB * NQ * CD * TT;

    // ---- load residual tile (vectorized, whole block) ----
    const float* zb = z + (size_t)b * DD * TT + t0;
    {
        float4* res4 = reinterpret_cast<float4*>(&sm.res[0][0]);
        for (int f = tid; f < DD * (TTILE / 4); f += NTHREADS) {
            int d = f >> 4, j = f & 15;
            res4[f] = reinterpret_cast<const float4*>(zb + (size_t)d * TT)[j];
        }
    }

    const int H    = tid >> 8;          // half id 0/1
    const int ht   = tid & 255;         // tid within half
    const int lt   = ht & 31;           // lane = local t (0..31)
    const int role = ht >> 5;           // warp role within half: channel/chunk/dgroup (0..7)
    const int tcol = H * HTILE + lt;    // absolute t column in tile (0..63)

    for (int q = 0; q < NQ; q++) {
        __syncthreads();   // rendezvous: res settled both halves; previous-q table use done
        // ---- load per-quantizer tables (whole block cooperative) ----
        {
            const float4* s1 = reinterpret_cast<const float4*>(g_win + (size_t)q * CD * DD);
            float4* d1 = reinterpret_cast<float4*>(&sm.win[0][0]);
            for (int i = tid; i < CD * DD / 4; i += NTHREADS) d1[i] = s1[i];
            const float4* s2 = reinterpret_cast<const float4*>(g_wout + (size_t)q * DD * CD);
            float4* d2 = reinterpret_cast<float4*>(&sm.wout[0][0]);
            for (int i = tid; i < DD * CD / 4; i += NTHREADS) d2[i] = s2[i];
            const float4* s3 = reinterpret_cast<const float4*>(g_cbn + (size_t)q * CS * CD);
            for (int i = tid; i < CS * 2; i += NTHREADS) sm.cbn4[i] = s3[i];
            const float4* s4 = reinterpret_cast<const float4*>(g_csq + (size_t)q * CS);
            for (int i = tid; i < CS / 4; i += NTHREADS) sm.csq4[i] = s4[i];
            const float4* s5 = reinterpret_cast<const float4*>(ob_g + (size_t)q * DD);
            float4* d5 = reinterpret_cast<float4*>(&sm.ob[0]);
            for (int i = tid; i < DD / 4; i += NTHREADS) d5[i] = s5[i];
            if (tid < CD) sm.ib[tid] = ib_g[q * CD + tid];
        }
        __syncthreads();

        // ================= per-half phases (halves drift independently) =================

        // ---- z_i = w_in @ residual + ib  (warp role = channel c, lane = t) ----
        float ziv;
        {
            const int c = role;
            const float4* wr4 = reinterpret_cast<const float4*>(sm.win[c]);
            float a0 = 0.f, a1 = 0.f, a2 = 0.f, a3 = 0.f;
            #pragma unroll 4
            for (int i = 0; i < DD / 4; i++) {
                float4 w = wr4[i];                  // broadcast LDS.128
                int d = 4 * i;
                a0 = fmaf(w.x, sm.res[d + 0][tcol], a0);
                a1 = fmaf(w.y, sm.res[d + 1][tcol], a1);
                a2 = fmaf(w.z, sm.res[d + 2][tcol], a2);
                a3 = fmaf(w.w, sm.res[d + 3][tcol], a3);
            }
            ziv = ((a0 + a1) + (a2 + a3)) + sm.ib[c];
            sm.zi[H][c][lt] = ziv;
            out_zis[(((size_t)b * NQ + q) * CD + c) * TT + t0 + tcol] = ziv;
        }
        bar_half(H);

        // ---- NN search: redundant per-thread norm, then 128 codes (chunk = role) ----
        {
            float z0 = sm.zi[H][0][lt], z1 = sm.zi[H][1][lt], z2 = sm.zi[H][2][lt], z3 = sm.zi[H][3][lt];
            float z4 = sm.zi[H][4][lt], z5 = sm.zi[H][5][lt], z6 = sm.zi[H][6][lt], z7 = sm.zi[H][7][lt];
            float ss = z0 * z0;
            ss = fmaf(z1, z1, ss); ss = fmaf(z2, z2, ss); ss = fmaf(z3, z3, ss);
            ss = fmaf(z4, z4, ss); ss = fmaf(z5, z5, ss); ss = fmaf(z6, z6, ss);
            ss = fmaf(z7, z7, ss);
            float den = fmaxf(__fsqrt_rn(ss), 1e-12f);
            float e0 = __fdiv_rn(z0, den), e1 = __fdiv_rn(z1, den);
            float e2 = __fdiv_rn(z2, den), e3 = __fdiv_rn(z3, den);
            float e4 = __fdiv_rn(z4, den), e5 = __fdiv_rn(z5, den);
            float e6 = __fdiv_rn(z6, den), e7 = __fdiv_rn(z7, den);
            float eq = e0 * e0;
            eq = fmaf(e1, e1, eq); eq = fmaf(e2, e2, eq); eq = fmaf(e3, e3, eq);
            eq = fmaf(e4, e4, eq); eq = fmaf(e5, e5, eq); eq = fmaf(e6, e6, eq);
            eq = fmaf(e7, e7, eq);

            const int s0 = role * (CS / 8);
            float b0 = FLT_MAX, b1 = FLT_MAX, b2 = FLT_MAX, b3 = FLT_MAX;
            int   i0 = 0, i1 = 0, i2 = 0, i3 = 0;
            #pragma unroll 2
            for (int s = s0; s < s0 + CS / 8; s += 4) {
                float4 cs4 = sm.csq4[s >> 2];       // broadcast LDS.128, 4 codes
                float dA = dist8(sm.cbn4[2 * s + 0], sm.cbn4[2 * s + 1], e0,e1,e2,e3,e4,e5,e6,e7, eq, cs4.x);
                float dB = dist8(sm.cbn4[2 * s + 2], sm.cbn4[2 * s + 3], e0,e1,e2,e3,e4,e5,e6,e7, eq, cs4.y);
                float dC = dist8(sm.cbn4[2 * s + 4], sm.cbn4[2 * s + 5], e0,e1,e2,e3,e4,e5,e6,e7, eq, cs4.z);
                float dDv= dist8(sm.cbn4[2 * s + 6], sm.cbn4[2 * s + 7], e0,e1,e2,e3,e4,e5,e6,e7, eq, cs4.w);
                if (dA < b0) { b0 = dA; i0 = s; }
                if (dB < b1) { b1 = dB; i1 = s + 1; }
                if (dC < b2) { b2 = dC; i2 = s + 2; }
                if (dDv< b3) { b3 = dDv; i3 = s + 3; }
            }
            // merge 4 strided chains, exact first-index tie-break
            if (b1 < b0 || (b1 == b0 && i1 < i0)) { b0 = b1; i0 = i1; }
            if (b2 < b0 || (b2 == b0 && i2 < i0)) { b0 = b2; i0 = i2; }
            if (b3 < b0 || (b3 == b0 && i3 < i0)) { b0 = b3; i0 = i3; }
            sm.redb[H][role][lt] = b0;
            sm.redi[H][role][lt] = i0;
        }
        bar_half(H);

        // ---- z_q: redundant argmin merge + straight-through  (warp role = channel c) ----
        {
            float bb = sm.redb[H][0][lt]; int bi = sm.redi[H][0][lt];
            #pragma unroll
            for (int g = 1; g < 8; g++) {
                float v = sm.redb[H][g][lt];
                if (v < bb) { bb = v; bi = sm.redi[H][g][lt]; }   // chunks ascending
            }
            if (role == 0)
                out_codes[((size_t)b * NQ + q) * TT + t0 + tcol] = (float)bi;
            float raw = __ldg(&cbraw[((size_t)q * CS + bi) * CD + role]);
            float zqv = ziv + (raw - ziv);
            sm.zqs[H][role][lt] = zqv;
            out_zqs[(((size_t)b * NQ + q) * CD + role) * TT + t0 + tcol] = zqv;
        }
        bar_half(H);

        // ---- z_o = w_out @ z_q + ob ; residual -= z_o  (warp role = dgroup, lane = t) ----
        {
            const float q0 = sm.zqs[H][0][lt], q1 = sm.zqs[H][1][lt], q2 = sm.zqs[H][2][lt], q3 = sm.zqs[H][3][lt];
            const float q4 = sm.zqs[H][4][lt], q5 = sm.zqs[H][5][lt], q6 = sm.zqs[H][6][lt], q7 = sm.zqs[H][7][lt];
            const float4* wo4 = reinterpret_cast<const float4*>(&sm.wout[0][0]);
            float* zosb = out_zos + (((size_t)b * NQ + q) * DD) * TT + t0 + tcol;
            const int dbase = role * 64;
            #pragma unroll 4
            for (int i = 0; i < 64; i++) {
                int d = dbase + i;
                float4 wa = wo4[2 * d], wb = wo4[2 * d + 1];
                float dot = q0 * wa.x;
                dot = fmaf(q1, wa.y, dot); dot = fmaf(q2, wa.z, dot); dot = fmaf(q3, wa.w, dot);
                dot = fmaf(q4, wb.x, dot); dot = fmaf(q5, wb.y, dot);
                dot = fmaf(q6, wb.z, dot); dot = fmaf(q7, wb.w, dot);
                float zo = dot + sm.ob[d];
                zosb[(size_t)d * TT] = zo;
                sm.res[d][tcol] = sm.res[d][tcol] - zo;
            }
        }
        // next loop iteration's __syncthreads() re-syncs both halves for table reload
    }

    __syncthreads();
    // ---- z_O = z - residual_final ----
    {
        const float* zsrc = zb + tcol;
        float* zOb = out_zO + (size_t)b * DD * TT + t0 + tcol;
        const int dbase = role * 64;
        #pragma unroll 4
        for (int i = 0; i < 64; i++) {
            int d = dbase + i;
            zOb[(size_t)d * TT] = zsrc[(size_t)d * TT] - sm.res[d][tcol];
        }
    }
}

extern "C" void kernel_launch(void* const* d_in, const int* in_sizes, int n_in,
                              void* d_out, int out_size) {
    const float* z    = (const float*)d_in[0];
    const float* in_v = (const float*)d_in[1];
    const float* in_g = (const float*)d_in[2];
    const float* in_b = (const float*)d_in[3];
    const float* out_v= (const float*)d_in[4];
    const float* out_g= (const float*)d_in[5];
    const float* out_b= (const float*)d_in[6];
    const float* cb   = (const float*)d_in[7];
    float* out = (float*)d_out;

    rvq_precompute<<<NQ, 256>>>(in_v, in_g, out_v, out_g, cb);

    cudaFuncSetAttribute(rvq_kernel, cudaFuncAttributeMaxDynamicSharedMemorySize,
                         (int)sizeof(SMem));
    dim3 grid(TT / TTILE, BB);
    rvq_kernel<<<grid, NTHREADS, sizeof(SMem)>>>(z, in_b, out_b, cb, out);
}